// round 2
// baseline (speedup 1.0000x reference)
#include <cuda_runtime.h>

#define NB 8
#define SEQ 1024
#define SFULL 1025
#define EMB 768
#define NH 12
#define HD 64
#define BH (NB*NH)   // 96

// Scratch (module-static device globals are allowed; runtime allocs are not)
__device__ float g_Q[NB*SEQ*EMB];
__device__ float g_K[NB*SEQ*EMB];
__device__ float g_V[NB*SEQ*EMB];
__device__ float g_Y[NB*SFULL*EMB];   // [cls_out ; values] rows, per batch 1025 rows
__device__ float g_C[NB*EMB];
__device__ float g_coef[BH*SEQ];
__device__ float g_ck[BH*SEQ];

// ---------------------------------------------------------------------------
// Fused Q/K/V projection:  C[M=8192, N=768] = xt[M,768] @ W^T + b
// xt row r maps to x row (r/1024)*1025 + 1 + (r%1024)
// 128x128x8 tile, 256 threads, 8x8 micro-tile (split 4+4, 64 apart)
// ---------------------------------------------------------------------------
__global__ __launch_bounds__(256) void qkv_gemm(
    const float* __restrict__ x,
    const float* __restrict__ Wq, const float* __restrict__ bq,
    const float* __restrict__ Wk, const float* __restrict__ bk,
    const float* __restrict__ Wv, const float* __restrict__ bv)
{
    const float* W; const float* bias; float* C;
    int z = blockIdx.z;
    if (z == 0)      { W = Wq; bias = bq; C = g_Q; }
    else if (z == 1) { W = Wk; bias = bk; C = g_K; }
    else             { W = Wv; bias = bv; C = g_V; }

    __shared__ float As[8][128];
    __shared__ float Bs[8][128];

    int tid = threadIdx.x;
    int ty = tid >> 4, tx = tid & 15;
    int lr = tid >> 1;
    int lc = (tid & 1) << 2;
    int bm = blockIdx.y << 7;
    int bn = blockIdx.x << 7;

    int ar = bm + lr;
    const float* Arow = x + (size_t)((ar >> 10) * SFULL + 1 + (ar & 1023)) * EMB;
    const float* Brow = W + (size_t)(bn + lr) * EMB;

    float acc[8][8];
#pragma unroll
    for (int i = 0; i < 8; i++)
#pragma unroll
        for (int j = 0; j < 8; j++) acc[i][j] = 0.f;

    for (int k0 = 0; k0 < EMB; k0 += 8) {
        float4 a4 = *(const float4*)(Arow + k0 + lc);
        float4 b4 = *(const float4*)(Brow + k0 + lc);
        __syncthreads();
        As[lc+0][lr] = a4.x; As[lc+1][lr] = a4.y; As[lc+2][lr] = a4.z; As[lc+3][lr] = a4.w;
        Bs[lc+0][lr] = b4.x; Bs[lc+1][lr] = b4.y; Bs[lc+2][lr] = b4.z; Bs[lc+3][lr] = b4.w;
        __syncthreads();
#pragma unroll
        for (int k = 0; k < 8; k++) {
            float4 a0 = *(const float4*)&As[k][ty*4];
            float4 a1 = *(const float4*)&As[k][64 + ty*4];
            float4 b0 = *(const float4*)&Bs[k][tx*4];
            float4 b1 = *(const float4*)&Bs[k][64 + tx*4];
            float ra[8] = {a0.x,a0.y,a0.z,a0.w,a1.x,a1.y,a1.z,a1.w};
            float rb[8] = {b0.x,b0.y,b0.z,b0.w,b1.x,b1.y,b1.z,b1.w};
#pragma unroll
            for (int i = 0; i < 8; i++)
#pragma unroll
                for (int j = 0; j < 8; j++)
                    acc[i][j] += ra[i] * rb[j];
        }
    }

#pragma unroll
    for (int i = 0; i < 8; i++) {
        int row = bm + ((i < 4) ? ty*4 + i : 64 + ty*4 + (i-4));
        float* crow = C + (size_t)row * EMB;
#pragma unroll
        for (int j = 0; j < 8; j++) {
            int col = bn + ((j < 4) ? tx*4 + j : 64 + tx*4 + (j-4));
            crow[col] = acc[i][j] + bias[col];
        }
    }
}

// ---------------------------------------------------------------------------
// Output projection: out[M=8200,768] = g_Y @ Wo^T + bo
// ---------------------------------------------------------------------------
__global__ __launch_bounds__(256) void out_gemm(
    const float* __restrict__ Wo, const float* __restrict__ bo,
    float* __restrict__ out)
{
    const int M = NB * SFULL; // 8200
    __shared__ float As[8][128];
    __shared__ float Bs[8][128];

    int tid = threadIdx.x;
    int ty = tid >> 4, tx = tid & 15;
    int lr = tid >> 1;
    int lc = (tid & 1) << 2;
    int bm = blockIdx.y << 7;
    int bn = blockIdx.x << 7;

    int ar = bm + lr;
    int arc = ar < M ? ar : (M - 1);
    const float* Arow = g_Y + (size_t)arc * EMB;
    const float* Brow = Wo + (size_t)(bn + lr) * EMB;

    float acc[8][8];
#pragma unroll
    for (int i = 0; i < 8; i++)
#pragma unroll
        for (int j = 0; j < 8; j++) acc[i][j] = 0.f;

    for (int k0 = 0; k0 < EMB; k0 += 8) {
        float4 a4 = *(const float4*)(Arow + k0 + lc);
        float4 b4 = *(const float4*)(Brow + k0 + lc);
        __syncthreads();
        As[lc+0][lr] = a4.x; As[lc+1][lr] = a4.y; As[lc+2][lr] = a4.z; As[lc+3][lr] = a4.w;
        Bs[lc+0][lr] = b4.x; Bs[lc+1][lr] = b4.y; Bs[lc+2][lr] = b4.z; Bs[lc+3][lr] = b4.w;
        __syncthreads();
#pragma unroll
        for (int k = 0; k < 8; k++) {
            float4 a0 = *(const float4*)&As[k][ty*4];
            float4 a1 = *(const float4*)&As[k][64 + ty*4];
            float4 b0 = *(const float4*)&Bs[k][tx*4];
            float4 b1 = *(const float4*)&Bs[k][64 + tx*4];
            float ra[8] = {a0.x,a0.y,a0.z,a0.w,a1.x,a1.y,a1.z,a1.w};
            float rb[8] = {b0.x,b0.y,b0.z,b0.w,b1.x,b1.y,b1.z,b1.w};
#pragma unroll
            for (int i = 0; i < 8; i++)
#pragma unroll
                for (int j = 0; j < 8; j++)
                    acc[i][j] += ra[i] * rb[j];
        }
    }

#pragma unroll
    for (int i = 0; i < 8; i++) {
        int row = bm + ((i < 4) ? ty*4 + i : 64 + ty*4 + (i-4));
        if (row >= M) continue;
        float* crow = out + (size_t)row * EMB;
#pragma unroll
        for (int j = 0; j < 8; j++) {
            int col = bn + ((j < 4) ? tx*4 + j : 64 + tx*4 + (j-4));
            crow[col] = acc[i][j] + bo[col];
        }
    }
}

// ---------------------------------------------------------------------------
// c projection: g_C[b,:] = x[b,0,:] @ Wc^T + bc
// ---------------------------------------------------------------------------
__global__ void cproj_kernel(const float* __restrict__ x,
                             const float* __restrict__ Wc,
                             const float* __restrict__ bc)
{
    int b = blockIdx.x;
    __shared__ float xs[EMB];
    for (int e = threadIdx.x; e < EMB; e += blockDim.x)
        xs[e] = x[(size_t)b * SFULL * EMB + e];
    __syncthreads();
    for (int j = threadIdx.x; j < EMB; j += blockDim.x) {
        const float* w = Wc + (size_t)j * EMB;
        float acc = bc[j];
        for (int e = 0; e < EMB; e++) acc += xs[e] * w[e];
        g_C[b * EMB + j] = acc;
    }
}

// ---------------------------------------------------------------------------
// Per-(b,h,t) coefficients. y==0: coef from Q; y==1: ck from K.
// One warp per (b,h,t). lane covers d and d+32.
// ---------------------------------------------------------------------------
__global__ __launch_bounds__(256) void coef_kernel()
{
    int gw = blockIdx.x * 8 + (threadIdx.x >> 5);   // 0..98303
    int lane = threadIdx.x & 31;
    int q = gw & (SEQ - 1);
    int bh = gw >> 10;
    int b = bh / NH, h = bh % NH;
    const float* src = (blockIdx.y == 0) ? g_Q : g_K;
    const float* qp = src + (size_t)(b * SEQ + q) * EMB + h * HD;
    const float* cp = g_C + b * EMB + h * HD;
    float q0 = qp[lane], q1 = qp[lane + 32];
    float c0 = cp[lane], c1 = cp[lane + 32];
    float qn = q0*q0 + q1*q1;
    float cq = c0*q0 + c1*q1;
    float cn = c0*c0 + c1*c1;
#pragma unroll
    for (int o = 16; o; o >>= 1) {
        qn += __shfl_xor_sync(0xffffffffu, qn, o);
        cq += __shfl_xor_sync(0xffffffffu, cq, o);
        cn += __shfl_xor_sync(0xffffffffu, cn, o);
    }
    if (lane == 0) {
        float cn2 = fmaxf(cn, 1e-5f);
        if (blockIdx.y == 0) {
            float qn2 = fmaxf(qn, 1e-5f);
            g_coef[gw] = cq / (qn2 * sqrtf(64.0f * cn2));
        } else {
            g_ck[gw] = cq / sqrtf(64.0f * cn2);
        }
    }
}

// ---------------------------------------------------------------------------
// Score GEMM: logits[bh, q, k] = (q . k) * coef[bh,q], raw logits -> attn buf
// per bh: M=N=1024, K=64. 128x128x8 tiles.
// ---------------------------------------------------------------------------
__global__ __launch_bounds__(256) void score_gemm(float* __restrict__ attn)
{
    int bh = blockIdx.z;
    int b = bh / NH, h = bh % NH;
    const float* Qb = g_Q + (size_t)b * SEQ * EMB + h * HD;
    const float* Kb = g_K + (size_t)b * SEQ * EMB + h * HD;
    float* Cb = attn + (size_t)bh * SEQ * SEQ;
    const float* coefp = g_coef + bh * SEQ;

    __shared__ float As[8][128];
    __shared__ float Bs[8][128];

    int tid = threadIdx.x;
    int ty = tid >> 4, tx = tid & 15;
    int lr = tid >> 1;
    int lc = (tid & 1) << 2;
    int bm = blockIdx.y << 7;
    int bn = blockIdx.x << 7;

    const float* Arow = Qb + (size_t)(bm + lr) * EMB;
    const float* Brow = Kb + (size_t)(bn + lr) * EMB;

    float acc[8][8];
#pragma unroll
    for (int i = 0; i < 8; i++)
#pragma unroll
        for (int j = 0; j < 8; j++) acc[i][j] = 0.f;

    for (int k0 = 0; k0 < HD; k0 += 8) {
        float4 a4 = *(const float4*)(Arow + k0 + lc);
        float4 b4 = *(const float4*)(Brow + k0 + lc);
        __syncthreads();
        As[lc+0][lr] = a4.x; As[lc+1][lr] = a4.y; As[lc+2][lr] = a4.z; As[lc+3][lr] = a4.w;
        Bs[lc+0][lr] = b4.x; Bs[lc+1][lr] = b4.y; Bs[lc+2][lr] = b4.z; Bs[lc+3][lr] = b4.w;
        __syncthreads();
#pragma unroll
        for (int k = 0; k < 8; k++) {
            float4 a0 = *(const float4*)&As[k][ty*4];
            float4 a1 = *(const float4*)&As[k][64 + ty*4];
            float4 b0 = *(const float4*)&Bs[k][tx*4];
            float4 b1 = *(const float4*)&Bs[k][64 + tx*4];
            float ra[8] = {a0.x,a0.y,a0.z,a0.w,a1.x,a1.y,a1.z,a1.w};
            float rb[8] = {b0.x,b0.y,b0.z,b0.w,b1.x,b1.y,b1.z,b1.w};
#pragma unroll
            for (int i = 0; i < 8; i++)
#pragma unroll
                for (int j = 0; j < 8; j++)
                    acc[i][j] += ra[i] * rb[j];
        }
    }

#pragma unroll
    for (int i = 0; i < 8; i++) {
        int row = bm + ((i < 4) ? ty*4 + i : 64 + ty*4 + (i-4));
        float cf = coefp[row];
        float* crow = Cb + (size_t)row * SEQ;
#pragma unroll
        for (int j = 0; j < 8; j++) {
            int col = bn + ((j < 4) ? tx*4 + j : 64 + tx*4 + (j-4));
            crow[col] = acc[i][j] * cf;
        }
    }
}

// ---------------------------------------------------------------------------
// In-place row softmax over attn rows of length 1024. One block per row.
// ---------------------------------------------------------------------------
__global__ __launch_bounds__(256) void softmax_kernel(float* __restrict__ attn)
{
    size_t row = blockIdx.x;
    float4* p = (float4*)(attn + row * SEQ);
    int t = threadIdx.x;
    int wid = t >> 5, lane = t & 31;
    __shared__ float redm[8], reds[8];

    float4 v = p[t];
    float m = fmaxf(fmaxf(v.x, v.y), fmaxf(v.z, v.w));
#pragma unroll
    for (int o = 16; o; o >>= 1) m = fmaxf(m, __shfl_xor_sync(0xffffffffu, m, o));
    if (lane == 0) redm[wid] = m;
    __syncthreads();
    m = redm[0];
#pragma unroll
    for (int i = 1; i < 8; i++) m = fmaxf(m, redm[i]);

    v.x = __expf(v.x - m); v.y = __expf(v.y - m);
    v.z = __expf(v.z - m); v.w = __expf(v.w - m);
    float s = v.x + v.y + v.z + v.w;
#pragma unroll
    for (int o = 16; o; o >>= 1) s += __shfl_xor_sync(0xffffffffu, s, o);
    if (lane == 0) reds[wid] = s;
    __syncthreads();
    s = reds[0];
#pragma unroll
    for (int i = 1; i < 8; i++) s += reds[i];

    float inv = 1.0f / s;
    v.x *= inv; v.y *= inv; v.z *= inv; v.w *= inv;
    p[t] = v;
}

// ---------------------------------------------------------------------------
// values = attn @ V  per (b,h): M=1024, N=64, K=1024. 64x64x16 tiles.
// Writes into g_Y rows 1..1024 of batch b at column h*64.
// ---------------------------------------------------------------------------
__global__ __launch_bounds__(256) void av_gemm(const float* __restrict__ attn)
{
    int bh = blockIdx.y;
    int b = bh / NH, h = bh % NH;
    const float* Ab = attn + (size_t)bh * SEQ * SEQ;
    const float* Vb = g_V + (size_t)b * SEQ * EMB + h * HD;
    int bm = blockIdx.x << 6;

    __shared__ float As[16][64];
    __shared__ float Bs[16][64];

    int tid = threadIdx.x;
    int ty = tid >> 4, tx = tid & 15;
    int a_r = tid >> 2, a_c = (tid & 3) << 2;
    int b_r = tid >> 4, b_c = (tid & 15) << 2;

    const float* Arow = Ab + (size_t)(bm + a_r) * SEQ;

    float acc[4][4];
#pragma unroll
    for (int i = 0; i < 4; i++)
#pragma unroll
        for (int j = 0; j < 4; j++) acc[i][j] = 0.f;

    for (int k0 = 0; k0 < SEQ; k0 += 16) {
        float4 a4 = *(const float4*)(Arow + k0 + a_c);
        float4 b4 = *(const float4*)(Vb + (size_t)(k0 + b_r) * EMB + b_c);
        __syncthreads();
        As[a_c+0][a_r] = a4.x; As[a_c+1][a_r] = a4.y;
        As[a_c+2][a_r] = a4.z; As[a_c+3][a_r] = a4.w;
        *(float4*)&Bs[b_r][b_c] = b4;
        __syncthreads();
#pragma unroll
        for (int k = 0; k < 16; k++) {
            float4 ra = *(const float4*)&As[k][ty*4];
            float4 rb = *(const float4*)&Bs[k][tx*4];
            float a[4] = {ra.x, ra.y, ra.z, ra.w};
            float bb[4] = {rb.x, rb.y, rb.z, rb.w};
#pragma unroll
            for (int i = 0; i < 4; i++)
#pragma unroll
                for (int j = 0; j < 4; j++)
                    acc[i][j] += a[i] * bb[j];
        }
    }

#pragma unroll
    for (int i = 0; i < 4; i++) {
        int row = bm + ty*4 + i;
        float* crow = g_Y + (size_t)(b * SFULL + 1 + row) * EMB + h * HD;
#pragma unroll
        for (int j = 0; j < 4; j++)
            crow[tx*4 + j] = acc[i][j];
    }
}

// ---------------------------------------------------------------------------
// CLS row: g_Y[b,0,:] = 0.5*(cls_token + sum_k ck[b,h,k]*V[b,k,h,:])
// ---------------------------------------------------------------------------
__global__ void cls_kernel(const float* __restrict__ x)
{
    int bh = blockIdx.x;
    int b = bh / NH, h = bh % NH;
    int d = threadIdx.x;  // 64 threads
    __shared__ float cks[SEQ];
    for (int k = d; k < SEQ; k += 64) cks[k] = g_ck[bh * SEQ + k];
    __syncthreads();
    const float* V = g_V + (size_t)b * SEQ * EMB + h * HD + d;
    float acc = 0.f;
#pragma unroll 8
    for (int k = 0; k < SEQ; k++) acc += cks[k] * V[(size_t)k * EMB];
    float cls = x[(size_t)b * SFULL * EMB + h * HD + d];
    g_Y[(size_t)b * SFULL * EMB + h * HD + d] = 0.5f * (cls + acc);
}

// ---------------------------------------------------------------------------

extern "C" void kernel_launch(void* const* d_in, const int* in_sizes, int n_in,
                              void* d_out, int out_size)
{
    const float* x  = (const float*)d_in[0];
    const float* Wq = (const float*)d_in[1]; const float* bq = (const float*)d_in[2];
    const float* Wk = (const float*)d_in[3]; const float* bk = (const float*)d_in[4];
    const float* Wv = (const float*)d_in[5]; const float* bv = (const float*)d_in[6];
    const float* Wc = (const float*)d_in[7]; const float* bc = (const float*)d_in[8];
    const float* Wo = (const float*)d_in[9]; const float* bo = (const float*)d_in[10];

    float* out  = (float*)d_out;
    float* attn = out + (size_t)NB * SFULL * EMB;   // attn written after out

    qkv_gemm<<<dim3(6, 64, 3), 256>>>(x, Wq, bq, Wk, bk, Wv, bv);
    cproj_kernel<<<8, 256>>>(x, Wc, bc);
    coef_kernel<<<dim3(12288, 2), 256>>>();
    score_gemm<<<dim3(8, 8, 96), 256>>>(attn);
    softmax_kernel<<<BH * SEQ, 256>>>(attn);
    av_gemm<<<dim3(16, 96), 256>>>(attn);
    cls_kernel<<<96, 64>>>(x);
    out_gemm<<<dim3(6, 65), 256>>>(Wo, bo, out);
}